// round 2
// baseline (speedup 1.0000x reference)
#include <cuda_runtime.h>
#include <math.h>

#define BATCH 8
#define NPTS  4096
#define HH    256
#define KOUT  1024
#define NC    63

// Scratch (static __device__ globals: allowed under the allocation guards)
__device__ int   g_members[BATCH][NPTS];
__device__ int   g_start[BATCH][NC];
__device__ int   g_count[BATCH][NC];
__device__ float g_k[BATCH * NPTS * 3];
__device__ float g_v[BATCH * NPTS * 3];

// ---------------------------------------------------------------------------
// Kernel 1: per-batch cluster counting sort + k/v projection precompute.
// One block per batch, 1024 threads.
// ---------------------------------------------------------------------------
__global__ __launch_bounds__(1024, 1)
void build_kernel(const float* __restrict__ x,
                  const int*   __restrict__ labels,
                  const float* __restrict__ Wk, const float* __restrict__ bk,
                  const float* __restrict__ Wv, const float* __restrict__ bv)
{
    const int b   = blockIdx.x;
    const int tid = threadIdx.x;

    __shared__ int hist[NC];
    __shared__ int offs[NC];
    if (tid < NC) hist[tid] = 0;
    __syncthreads();

    // 3x3 projection weights into registers
    float wk[9], wv[9], bk3[3], bv3[3];
#pragma unroll
    for (int i = 0; i < 9; i++) { wk[i] = Wk[i]; wv[i] = Wv[i]; }
#pragma unroll
    for (int i = 0; i < 3; i++) { bk3[i] = bk[i]; bv3[i] = bv[i]; }

    const int* lab = labels + b * NPTS;

    for (int n = tid; n < NPTS; n += 1024) {
        int l = lab[n];
        if (l >= 0) atomicAdd(&hist[l], 1);

        const float* xv = x + ((size_t)(b * NPTS + n)) * 3;
        float x0 = xv[0], x1 = xv[1], x2 = xv[2];

        float* kp = g_k + (size_t)(b * NPTS + n) * 3;
        kp[0] = fmaf(wk[0], x0, fmaf(wk[1], x1, fmaf(wk[2], x2, bk3[0])));
        kp[1] = fmaf(wk[3], x0, fmaf(wk[4], x1, fmaf(wk[5], x2, bk3[1])));
        kp[2] = fmaf(wk[6], x0, fmaf(wk[7], x1, fmaf(wk[8], x2, bk3[2])));

        float* vp = g_v + (size_t)(b * NPTS + n) * 3;
        vp[0] = fmaf(wv[0], x0, fmaf(wv[1], x1, fmaf(wv[2], x2, bv3[0])));
        vp[1] = fmaf(wv[3], x0, fmaf(wv[4], x1, fmaf(wv[5], x2, bv3[1])));
        vp[2] = fmaf(wv[6], x0, fmaf(wv[7], x1, fmaf(wv[8], x2, bv3[2])));
    }
    __syncthreads();

    // Exclusive prefix over 63 bins (single thread; trivial)
    if (tid == 0) {
        int acc = 0;
        for (int c = 0; c < NC; c++) {
            g_start[b][c] = acc;
            g_count[b][c] = hist[c];
            offs[c] = acc;
            acc += hist[c];
        }
    }
    __syncthreads();

    // Scatter member indices (order within a cluster is softmax-irrelevant
    // beyond fp rounding << 1e-3 tolerance)
    for (int n = tid; n < NPTS; n += 1024) {
        int l = lab[n];
        if (l >= 0) {
            int p = atomicAdd(&offs[l], 1);
            g_members[b][p] = n;
        }
    }
}

// ---------------------------------------------------------------------------
// Kernel 2: one warp per output query row.
// Cluster-restricted online-softmax attention + out_proj + MLP (3->256->3).
// Block = 128 threads (4 warps); grid = 8*1024/4 = 2048 blocks.
// ---------------------------------------------------------------------------
__global__ __launch_bounds__(128)
void attn_mlp_kernel(const float* __restrict__ x,
                     const int*   __restrict__ labels,
                     const float* __restrict__ Wq, const float* __restrict__ bq,
                     const float* __restrict__ Wo, const float* __restrict__ bo,
                     const float* __restrict__ W1, const float* __restrict__ b1,
                     const float* __restrict__ W2, const float* __restrict__ b2,
                     float* __restrict__ out)
{
    __shared__ float sW1[HH * 3];
    __shared__ float sW2[3 * HH];
    __shared__ float sb1[HH];

    const int tid = threadIdx.x;
    for (int i = tid; i < HH * 3; i += 128) { sW1[i] = W1[i]; sW2[i] = W2[i]; }
    for (int i = tid; i < HH; i += 128) sb1[i] = b1[i];
    __syncthreads();

    const int warp = tid >> 5;
    const int lane = tid & 31;
    const int qid  = blockIdx.x * 4 + warp;   // 0 .. 8191
    const int b    = qid >> 10;               // batch
    const int n    = qid & 1023;              // query row (only first KOUT emitted)

    const int l = labels[b * NPTS + n];

    float c0 = 0.f, c1 = 0.f, c2 = 0.f;      // attention context (0 for noise)

    if (l >= 0) {
        const float* xv = x + (size_t)(b * NPTS + n) * 3;
        float x0 = xv[0], x1 = xv[1], x2 = xv[2];
        const float scale = 0.57735026919f;  // 1/sqrt(3)
        float q0 = (fmaf(Wq[0], x0, fmaf(Wq[1], x1, fmaf(Wq[2], x2, bq[0])))) * scale;
        float q1 = (fmaf(Wq[3], x0, fmaf(Wq[4], x1, fmaf(Wq[5], x2, bq[1])))) * scale;
        float q2 = (fmaf(Wq[6], x0, fmaf(Wq[7], x1, fmaf(Wq[8], x2, bq[2])))) * scale;

        const int st  = g_start[b][l];
        const int cnt = g_count[b][l];

        // Per-lane online softmax over strided member list
        float mx = -INFINITY, sm = 0.f, a0 = 0.f, a1 = 0.f, a2 = 0.f;
        for (int i = lane; i < cnt; i += 32) {
            int m = g_members[b][st + i];
            const float* kp = g_k + (size_t)(b * NPTS + m) * 3;
            const float* vp = g_v + (size_t)(b * NPTS + m) * 3;
            float s = fmaf(q0, kp[0], fmaf(q1, kp[1], q2 * kp[2]));
            float mn = fmaxf(mx, s);
            float corr = __expf(mx - mn);   // first iter: exp(-inf)=0, kills stale 0 state safely
            float e    = __expf(s - mn);
            sm = fmaf(sm, corr, e);
            a0 = fmaf(a0, corr, e * vp[0]);
            a1 = fmaf(a1, corr, e * vp[1]);
            a2 = fmaf(a2, corr, e * vp[2]);
            mx = mn;
        }

        // Warp-tree merge of (mx, sm, a*) online-softmax states
#pragma unroll
        for (int off = 16; off; off >>= 1) {
            float mx2 = __shfl_down_sync(0xffffffffu, mx, off);
            float sm2 = __shfl_down_sync(0xffffffffu, sm, off);
            float t0  = __shfl_down_sync(0xffffffffu, a0, off);
            float t1  = __shfl_down_sync(0xffffffffu, a1, off);
            float t2  = __shfl_down_sync(0xffffffffu, a2, off);
            float mn = fmaxf(mx, mx2);
            float ca = (mx  > -INFINITY) ? __expf(mx  - mn) : 0.f;
            float cb = (mx2 > -INFINITY) ? __expf(mx2 - mn) : 0.f;
            sm = sm * ca + sm2 * cb;
            a0 = a0 * ca + t0 * cb;
            a1 = a1 * ca + t1 * cb;
            a2 = a2 * ca + t2 * cb;
            mx = mn;
        }
        // Broadcast lane-0 result to all lanes
        sm = __shfl_sync(0xffffffffu, sm, 0);
        a0 = __shfl_sync(0xffffffffu, a0, 0);
        a1 = __shfl_sync(0xffffffffu, a1, 0);
        a2 = __shfl_sync(0xffffffffu, a2, 0);
        float inv = 1.f / sm;                 // sm > 0: query is its own member
        c0 = a0 * inv; c1 = a1 * inv; c2 = a2 * inv;
    }

    // out_proj (redundant per lane; 9 FMA)
    float o0 = fmaf(Wo[0], c0, fmaf(Wo[1], c1, fmaf(Wo[2], c2, bo[0])));
    float o1 = fmaf(Wo[3], c0, fmaf(Wo[4], c1, fmaf(Wo[5], c2, bo[1])));
    float o2 = fmaf(Wo[6], c0, fmaf(Wo[7], c1, fmaf(Wo[8], c2, bo[2])));

    // MLP: 8 hidden units per lane
    float y0 = 0.f, y1 = 0.f, y2 = 0.f;
#pragma unroll
    for (int t = 0; t < HH / 32; t++) {
        int j = lane + t * 32;
        float h = fmaf(sW1[j * 3 + 0], o0,
                  fmaf(sW1[j * 3 + 1], o1,
                  fmaf(sW1[j * 3 + 2], o2, sb1[j])));
        h = fmaxf(h, 0.f);
        y0 = fmaf(sW2[         j], h, y0);
        y1 = fmaf(sW2[HH     + j], h, y1);
        y2 = fmaf(sW2[2 * HH + j], h, y2);
    }
#pragma unroll
    for (int off = 16; off; off >>= 1) {
        y0 += __shfl_down_sync(0xffffffffu, y0, off);
        y1 += __shfl_down_sync(0xffffffffu, y1, off);
        y2 += __shfl_down_sync(0xffffffffu, y2, off);
    }
    if (lane == 0) {
        float* op = out + (size_t)(b * KOUT + n) * 3;
        op[0] = y0 + b2[0];
        op[1] = y1 + b2[1];
        op[2] = y2 + b2[2];
    }
}

// ---------------------------------------------------------------------------
extern "C" void kernel_launch(void* const* d_in, const int* in_sizes, int n_in,
                              void* d_out, int out_size)
{
    const float* x      = (const float*)d_in[0];
    const int*   labels = (const int*)  d_in[1];
    const float* Wq = (const float*)d_in[2];
    const float* bq = (const float*)d_in[3];
    const float* Wk = (const float*)d_in[4];
    const float* bk = (const float*)d_in[5];
    const float* Wv = (const float*)d_in[6];
    const float* bv = (const float*)d_in[7];
    const float* Wo = (const float*)d_in[8];
    const float* bo = (const float*)d_in[9];
    const float* W1 = (const float*)d_in[10];
    const float* b1 = (const float*)d_in[11];
    const float* W2 = (const float*)d_in[12];
    const float* b2 = (const float*)d_in[13];
    float* out = (float*)d_out;

    build_kernel<<<BATCH, 1024>>>(x, labels, Wk, bk, Wv, bv);
    attn_mlp_kernel<<<(BATCH * KOUT) / 4, 128>>>(x, labels, Wq, bq, Wo, bo,
                                                 W1, b1, W2, b2, out);
}

// round 3
// speedup vs baseline: 1.2609x; 1.2609x over previous
#include <cuda_runtime.h>
#include <math.h>

#define BATCH 8
#define NPTS  4096
#define HH    256
#define KOUT  1024
#define NC    63

// Scratch (static __device__ globals: allowed under the allocation guards)
__device__ int   g_start[BATCH][NC];
__device__ int   g_count[BATCH][NC];
__device__ int   g_offs [BATCH][NC];
// Cluster-sorted SoA k/v (written by scatter kernel, read coalesced by attn)
__device__ float g_sk0[BATCH * NPTS];
__device__ float g_sk1[BATCH * NPTS];
__device__ float g_sk2[BATCH * NPTS];
__device__ float g_sv0[BATCH * NPTS];
__device__ float g_sv1[BATCH * NPTS];
__device__ float g_sv2[BATCH * NPTS];

// ---------------------------------------------------------------------------
// K1: per-batch histogram + exclusive prefix. One block per batch.
// ---------------------------------------------------------------------------
__global__ __launch_bounds__(1024, 1)
void hist_kernel(const int* __restrict__ labels)
{
    const int b   = blockIdx.x;
    const int tid = threadIdx.x;

    __shared__ int hist[NC];
    if (tid < NC) hist[tid] = 0;
    __syncthreads();

    const int* lab = labels + b * NPTS;
    for (int n = tid; n < NPTS; n += 1024) {
        int l = lab[n];
        if (l >= 0) atomicAdd(&hist[l], 1);
    }
    __syncthreads();

    if (tid == 0) {
        int acc = 0;
        for (int c = 0; c < NC; c++) {
            g_start[b][c] = acc;
            g_offs [b][c] = acc;
            g_count[b][c] = hist[c];
            acc += hist[c];
        }
    }
}

// ---------------------------------------------------------------------------
// K2: wide scatter — fused k/v projection + write into cluster-sorted SoA.
// Grid-stride over all B*N points.
// ---------------------------------------------------------------------------
__global__ __launch_bounds__(256)
void scatter_kernel(const float* __restrict__ x,
                    const int*   __restrict__ labels,
                    const float* __restrict__ Wk, const float* __restrict__ bk,
                    const float* __restrict__ Wv, const float* __restrict__ bv)
{
    // 3x3 weights: every lane reads same addr -> broadcast, L1-hot
    float wk[9], wv[9], bk3[3], bv3[3];
#pragma unroll
    for (int i = 0; i < 9; i++) { wk[i] = __ldg(Wk + i); wv[i] = __ldg(Wv + i); }
#pragma unroll
    for (int i = 0; i < 3; i++) { bk3[i] = __ldg(bk + i); bv3[i] = __ldg(bv + i); }

    const int total = BATCH * NPTS;
    for (int idx = blockIdx.x * blockDim.x + threadIdx.x; idx < total;
         idx += gridDim.x * blockDim.x) {
        const int b = idx >> 12;          // / NPTS
        const int l = labels[idx];
        if (l < 0) continue;

        const float* xv = x + (size_t)idx * 3;
        float x0 = xv[0], x1 = xv[1], x2 = xv[2];

        int p = atomicAdd(&g_offs[b][l], 1);     // batch-local sorted position
        int pos = b * NPTS + p;

        g_sk0[pos] = fmaf(wk[0], x0, fmaf(wk[1], x1, fmaf(wk[2], x2, bk3[0])));
        g_sk1[pos] = fmaf(wk[3], x0, fmaf(wk[4], x1, fmaf(wk[5], x2, bk3[1])));
        g_sk2[pos] = fmaf(wk[6], x0, fmaf(wk[7], x1, fmaf(wk[8], x2, bk3[2])));
        g_sv0[pos] = fmaf(wv[0], x0, fmaf(wv[1], x1, fmaf(wv[2], x2, bv3[0])));
        g_sv1[pos] = fmaf(wv[3], x0, fmaf(wv[4], x1, fmaf(wv[5], x2, bv3[1])));
        g_sv2[pos] = fmaf(wv[6], x0, fmaf(wv[7], x1, fmaf(wv[8], x2, bv3[2])));
    }
}

// ---------------------------------------------------------------------------
// K3: one warp per output query row. Coalesced sorted-SoA k/v reads.
// MLP weights read straight through L1 (no smem staging, no __syncthreads).
// Block = 256 threads (8 warps); grid = 8*1024/8 = 1024 blocks.
// ---------------------------------------------------------------------------
__global__ __launch_bounds__(256)
void attn_mlp_kernel(const float* __restrict__ x,
                     const int*   __restrict__ labels,
                     const float* __restrict__ Wq, const float* __restrict__ bq,
                     const float* __restrict__ Wo, const float* __restrict__ bo,
                     const float* __restrict__ W1, const float* __restrict__ b1,
                     const float* __restrict__ W2, const float* __restrict__ b2,
                     float* __restrict__ out)
{
    const int tid  = threadIdx.x;
    const int warp = tid >> 5;
    const int lane = tid & 31;
    const int qid  = blockIdx.x * 8 + warp;   // 0 .. 8191
    const int b    = qid >> 10;               // batch
    const int n    = qid & 1023;              // query row (first KOUT only)

    const int l = labels[b * NPTS + n];

    float c0 = 0.f, c1 = 0.f, c2 = 0.f;       // attention context (0 for noise)

    if (l >= 0) {
        const float* xv = x + (size_t)(b * NPTS + n) * 3;
        float x0 = xv[0], x1 = xv[1], x2 = xv[2];
        const float scale = 0.57735026919f;   // 1/sqrt(3)
        float q0 = fmaf(__ldg(Wq+0), x0, fmaf(__ldg(Wq+1), x1, fmaf(__ldg(Wq+2), x2, __ldg(bq+0)))) * scale;
        float q1 = fmaf(__ldg(Wq+3), x0, fmaf(__ldg(Wq+4), x1, fmaf(__ldg(Wq+5), x2, __ldg(bq+1)))) * scale;
        float q2 = fmaf(__ldg(Wq+6), x0, fmaf(__ldg(Wq+7), x1, fmaf(__ldg(Wq+8), x2, __ldg(bq+2)))) * scale;

        const int st  = g_start[b][l] + b * NPTS;
        const int cnt = g_count[b][l];

        // Per-lane online softmax over the coalesced sorted member range
        float mx = -INFINITY, sm = 0.f, a0 = 0.f, a1 = 0.f, a2 = 0.f;
        for (int i = lane; i < cnt; i += 32) {
            int p = st + i;
            float s = fmaf(q0, g_sk0[p], fmaf(q1, g_sk1[p], q2 * g_sk2[p]));
            float v0 = g_sv0[p], v1 = g_sv1[p], v2 = g_sv2[p];
            float mn = fmaxf(mx, s);
            float corr = __expf(mx - mn);   // first iter: exp(-inf)=0 kills stale state
            float e    = __expf(s - mn);
            sm = fmaf(sm, corr, e);
            a0 = fmaf(a0, corr, e * v0);
            a1 = fmaf(a1, corr, e * v1);
            a2 = fmaf(a2, corr, e * v2);
            mx = mn;
        }

        // Warp-tree merge of online-softmax states
#pragma unroll
        for (int off = 16; off; off >>= 1) {
            float mx2 = __shfl_down_sync(0xffffffffu, mx, off);
            float sm2 = __shfl_down_sync(0xffffffffu, sm, off);
            float t0  = __shfl_down_sync(0xffffffffu, a0, off);
            float t1  = __shfl_down_sync(0xffffffffu, a1, off);
            float t2  = __shfl_down_sync(0xffffffffu, a2, off);
            float mn = fmaxf(mx, mx2);
            float ca = (mx  > -INFINITY) ? __expf(mx  - mn) : 0.f;
            float cb = (mx2 > -INFINITY) ? __expf(mx2 - mn) : 0.f;
            sm = sm * ca + sm2 * cb;
            a0 = a0 * ca + t0 * cb;
            a1 = a1 * ca + t1 * cb;
            a2 = a2 * ca + t2 * cb;
            mx = mn;
        }
        sm = __shfl_sync(0xffffffffu, sm, 0);
        a0 = __shfl_sync(0xffffffffu, a0, 0);
        a1 = __shfl_sync(0xffffffffu, a1, 0);
        a2 = __shfl_sync(0xffffffffu, a2, 0);
        float inv = 1.f / sm;                 // sm > 0: query is its own member
        c0 = a0 * inv; c1 = a1 * inv; c2 = a2 * inv;
    }

    // out_proj (redundant per lane; 9 FMA, broadcast loads)
    float o0 = fmaf(__ldg(Wo+0), c0, fmaf(__ldg(Wo+1), c1, fmaf(__ldg(Wo+2), c2, __ldg(bo+0))));
    float o1 = fmaf(__ldg(Wo+3), c0, fmaf(__ldg(Wo+4), c1, fmaf(__ldg(Wo+5), c2, __ldg(bo+1))));
    float o2 = fmaf(__ldg(Wo+6), c0, fmaf(__ldg(Wo+7), c1, fmaf(__ldg(Wo+8), c2, __ldg(bo+2))));

    // MLP 3->256->3: 8 hidden units per lane, weights through L1
    float y0 = 0.f, y1 = 0.f, y2 = 0.f;
#pragma unroll
    for (int t = 0; t < HH / 32; t++) {
        int j = lane + t * 32;
        float h = fmaf(__ldg(W1 + j * 3 + 0), o0,
                  fmaf(__ldg(W1 + j * 3 + 1), o1,
                  fmaf(__ldg(W1 + j * 3 + 2), o2, __ldg(b1 + j))));
        h = fmaxf(h, 0.f);
        y0 = fmaf(__ldg(W2 +          j), h, y0);
        y1 = fmaf(__ldg(W2 + HH     + j), h, y1);
        y2 = fmaf(__ldg(W2 + 2 * HH + j), h, y2);
    }
#pragma unroll
    for (int off = 16; off; off >>= 1) {
        y0 += __shfl_down_sync(0xffffffffu, y0, off);
        y1 += __shfl_down_sync(0xffffffffu, y1, off);
        y2 += __shfl_down_sync(0xffffffffu, y2, off);
    }
    if (lane == 0) {
        float* op = out + (size_t)(b * KOUT + n) * 3;
        op[0] = y0 + __ldg(b2 + 0);
        op[1] = y1 + __ldg(b2 + 1);
        op[2] = y2 + __ldg(b2 + 2);
    }
}

// ---------------------------------------------------------------------------
extern "C" void kernel_launch(void* const* d_in, const int* in_sizes, int n_in,
                              void* d_out, int out_size)
{
    const float* x      = (const float*)d_in[0];
    const int*   labels = (const int*)  d_in[1];
    const float* Wq = (const float*)d_in[2];
    const float* bq = (const float*)d_in[3];
    const float* Wk = (const float*)d_in[4];
    const float* bk = (const float*)d_in[5];
    const float* Wv = (const float*)d_in[6];
    const float* bv = (const float*)d_in[7];
    const float* Wo = (const float*)d_in[8];
    const float* bo = (const float*)d_in[9];
    const float* W1 = (const float*)d_in[10];
    const float* b1 = (const float*)d_in[11];
    const float* W2 = (const float*)d_in[12];
    const float* b2 = (const float*)d_in[13];
    float* out = (float*)d_out;

    hist_kernel<<<BATCH, 1024>>>(labels);
    scatter_kernel<<<128, 256>>>(x, labels, Wk, bk, Wv, bv);
    attn_mlp_kernel<<<(BATCH * KOUT) / 8, 256>>>(x, labels, Wq, bq, Wo, bo,
                                                 W1, b1, W2, b2, out);
}